// round 1
// baseline (speedup 1.0000x reference)
#include <cuda_runtime.h>

#define Bc   4
#define Sc   1024
#define Dc   1024
#define Hc   16
#define DHc  64
#define DFFc 4096
#define DLATc 256
#define Mrows (Bc * Sc)   // 4096

// ---------------- scratch (no cudaMalloc allowed) ----------------
__device__ float g_Q [Bc * Sc * Dc];
__device__ float g_K [Bc * Sc * Dc];
__device__ float g_V [Bc * Sc * Dc];
__device__ float g_O [Bc * Sc * Dc];
__device__ float g_O2[Bc * Sc * Dc];
__device__ float g_H [Bc * Sc * DFFc];
__device__ float g_F [Bc * Sc * Dc];

// ---------------- generic tiled fp32 GEMM ----------------
// C[M,N] = op(A[M,K] @ W[K,N] (+bias) (relu))
// AMODE 0: A row-major stride K.
// AMODE 1: logical A = concat(out2[M,1024], z[row>>10, 256]) (K = 1280).
template<int AMODE, bool RELU, bool BIAS>
__global__ void __launch_bounds__(256) gemm_kernel(
    const float* __restrict__ A, const float* __restrict__ Z,
    const float* __restrict__ W, const float* __restrict__ bias,
    float* __restrict__ C, int M, int N, int K)
{
    __shared__ float As[8][128];
    __shared__ float Bs[8][128];
    const int tid  = threadIdx.x;
    const int row0 = blockIdx.y * 128;
    const int col0 = blockIdx.x * 128;
    const int tx = tid & 15;
    const int ty = tid >> 4;
    const int a_row = tid >> 1;
    const int a_col = (tid & 1) << 2;
    const int b_row = tid >> 5;
    const int b_col = (tid & 31) << 2;

    float acc[8][8];
#pragma unroll
    for (int i = 0; i < 8; i++)
#pragma unroll
        for (int j = 0; j < 8; j++) acc[i][j] = 0.f;

    for (int k0 = 0; k0 < K; k0 += 8) {
        float4 av;
        if (AMODE == 0) {
            av = *(const float4*)(A + (size_t)(row0 + a_row) * K + (k0 + a_col));
        } else {
            int kc = k0 + a_col;
            if (kc < Dc)
                av = *(const float4*)(A + (size_t)(row0 + a_row) * Dc + kc);
            else
                av = *(const float4*)(Z + (size_t)((row0 + a_row) >> 10) * DLATc + (kc - Dc));
        }
        As[a_col + 0][a_row] = av.x;
        As[a_col + 1][a_row] = av.y;
        As[a_col + 2][a_row] = av.z;
        As[a_col + 3][a_row] = av.w;
        *(float4*)(&Bs[b_row][b_col]) =
            *(const float4*)(W + (size_t)(k0 + b_row) * N + (col0 + b_col));
        __syncthreads();
#pragma unroll
        for (int kk = 0; kk < 8; kk++) {
            float rm[8], rn[8];
#pragma unroll
            for (int i = 0; i < 8; i++) rm[i] = As[kk][ty * 8 + i];
#pragma unroll
            for (int j = 0; j < 8; j++) rn[j] = Bs[kk][tx * 8 + j];
#pragma unroll
            for (int i = 0; i < 8; i++)
#pragma unroll
                for (int j = 0; j < 8; j++) acc[i][j] += rm[i] * rn[j];
        }
        __syncthreads();
    }

#pragma unroll
    for (int i = 0; i < 8; i++) {
        const int r = row0 + ty * 8 + i;
#pragma unroll
        for (int j = 0; j < 8; j += 4) {
            const int c = col0 + tx * 8 + j;
            float4 v;
            v.x = acc[i][j]; v.y = acc[i][j + 1]; v.z = acc[i][j + 2]; v.w = acc[i][j + 3];
            if (BIAS) {
                v.x += bias[c]; v.y += bias[c + 1]; v.z += bias[c + 2]; v.w += bias[c + 3];
            }
            if (RELU) {
                v.x = fmaxf(v.x, 0.f); v.y = fmaxf(v.y, 0.f);
                v.z = fmaxf(v.z, 0.f); v.w = fmaxf(v.w, 0.f);
            }
            *(float4*)(C + (size_t)r * N + c) = v;
        }
    }
}

// ---------------- flash attention (fp32, causal + key padding mask) ----------------
// grid (S/64, H, B), 256 threads. Thread (q = tid>>2, g = tid&3) owns output
// dims [g*16, g*16+16) of query q0+q. K and V share one smem tile.
__global__ void __launch_bounds__(256) attn_kernel(
    const float* __restrict__ Q, const float* __restrict__ K,
    const float* __restrict__ V, const int* __restrict__ mask,
    float* __restrict__ O)
{
    __shared__ float KVs[64][65];
    __shared__ float Ss[64][65];
    __shared__ int   km[64];
    const int qt = blockIdx.x, h = blockIdx.y, b = blockIdx.z;
    const int q0 = qt * 64;
    const int tid = threadIdx.x;
    const int q = tid >> 2, g = tid & 3;
    const size_t base = ((size_t)b * Sc) * Dc + (size_t)h * DHc;

    // q row into registers (4 lanes share a row -> L1 broadcast)
    float qreg[64];
    {
        const float* qp = Q + base + (size_t)(q0 + q) * Dc;
#pragma unroll
        for (int c = 0; c < 64; c += 4) {
            float4 v4 = *(const float4*)(qp + c);
            qreg[c] = v4.x; qreg[c + 1] = v4.y; qreg[c + 2] = v4.z; qreg[c + 3] = v4.w;
        }
    }
    const int mq = mask[b * Sc + q0 + q];

    float m = -1e30f, l = 0.f;
    float acc[16];
#pragma unroll
    for (int i = 0; i < 16; i++) acc[i] = 0.f;

    for (int kt = 0; kt <= qt; kt++) {
        const int k0 = kt * 64;
        __syncthreads();                    // prior AV reads of KVs done
        for (int i = tid; i < 64 * 16; i += 256) {
            int r = i >> 4, c = (i & 15) << 2;
            float4 v4 = *(const float4*)(K + base + (size_t)(k0 + r) * Dc + c);
            KVs[r][c] = v4.x; KVs[r][c + 1] = v4.y; KVs[r][c + 2] = v4.z; KVs[r][c + 3] = v4.w;
        }
        if (tid < 64) km[tid] = mask[b * Sc + k0 + tid];
        __syncthreads();

        float sv[16];
#pragma unroll
        for (int j = 0; j < 16; j++) sv[j] = 0.f;
#pragma unroll
        for (int dd = 0; dd < 64; dd += 4) {
#pragma unroll
            for (int j = 0; j < 16; j++) {
                float4 kv = *(const float4*)(&KVs[g * 16 + j][dd]);
                sv[j] += qreg[dd] * kv.x + qreg[dd + 1] * kv.y
                       + qreg[dd + 2] * kv.z + qreg[dd + 3] * kv.w;
            }
        }
        float mt = -1e30f;
#pragma unroll
        for (int j = 0; j < 16; j++) {
            const int kk = g * 16 + j;
            float s = sv[j] * 0.125f;                      // 1/sqrt(64)
            if ((k0 + kk) > (q0 + q) || km[kk] == 0) s = -1e30f;
            sv[j] = s;
            mt = fmaxf(mt, s);
        }
        mt = fmaxf(mt, __shfl_xor_sync(0xffffffffu, mt, 1));
        mt = fmaxf(mt, __shfl_xor_sync(0xffffffffu, mt, 2));
        const float mnew  = fmaxf(m, mt);
        const float scale = __expf(m - mnew);
        float lt = 0.f;
#pragma unroll
        for (int j = 0; j < 16; j++) {
            float p = __expf(sv[j] - mnew);
            lt += p;
            Ss[q][g * 16 + j] = p;
        }
        lt += __shfl_xor_sync(0xffffffffu, lt, 1);
        lt += __shfl_xor_sync(0xffffffffu, lt, 2);
        l = l * scale + lt;
        m = mnew;
#pragma unroll
        for (int i = 0; i < 16; i++) acc[i] *= scale;
        __syncwarp();
        __syncthreads();                    // scores consumed KVs(K); reload as V
        for (int i = tid; i < 64 * 16; i += 256) {
            int r = i >> 4, c = (i & 15) << 2;
            float4 v4 = *(const float4*)(V + base + (size_t)(k0 + r) * Dc + c);
            KVs[r][c] = v4.x; KVs[r][c + 1] = v4.y; KVs[r][c + 2] = v4.z; KVs[r][c + 3] = v4.w;
        }
        __syncthreads();
#pragma unroll 8
        for (int k = 0; k < 64; k++) {
            const float p = Ss[q][k];
#pragma unroll
            for (int i = 0; i < 16; i++) acc[i] += p * KVs[k][g * 16 + i];
        }
    }

    // padded query rows -> exact 0 (reference multiplies o by mask_q)
    const float inv = (mq != 0) ? (1.0f / l) : 0.f;
    float* op = O + base + (size_t)(q0 + q) * Dc + g * 16;
#pragma unroll
    for (int i = 0; i < 16; i += 4) {
        float4 v;
        v.x = acc[i] * inv; v.y = acc[i + 1] * inv;
        v.z = acc[i + 2] * inv; v.w = acc[i + 3] * inv;
        *(float4*)(op + i) = v;
    }
}

// ---------------- layernorm helpers ----------------
__device__ __forceinline__ float block_sum(float v, float* red) {
#pragma unroll
    for (int o = 16; o > 0; o >>= 1) v += __shfl_xor_sync(0xffffffffu, v, o);
    const int lane = threadIdx.x & 31, w = threadIdx.x >> 5;
    __syncthreads();
    if (lane == 0) red[w] = v;
    __syncthreads();
    float s = 0.f;
#pragma unroll
    for (int i = 0; i < 8; i++) s += red[i];
    return s;
}

// out2 = LN2( LN1(x + o) + cond )   (ln1 output feeds nothing else)
__global__ void __launch_bounds__(256) ln12_kernel(
    const float* __restrict__ x, const float* __restrict__ o,
    const float* __restrict__ cond,
    const float* __restrict__ g1, const float* __restrict__ b1,
    const float* __restrict__ g2, const float* __restrict__ b2,
    float* __restrict__ out2)
{
    __shared__ float red[8];
    const int row = blockIdx.x;
    const int bb  = row >> 10;
    const int tid = threadIdx.x;
    const float* xr = x + (size_t)row * Dc;
    const float* orr = o + (size_t)row * Dc;
    float t[4];
    float s = 0.f;
#pragma unroll
    for (int k = 0; k < 4; k++) {
        const int d = tid + k * 256;
        t[k] = xr[d] + orr[d];
        s += t[k];
    }
    float mu = block_sum(s, red) * (1.f / 1024.f);
    float vs = 0.f;
#pragma unroll
    for (int k = 0; k < 4; k++) { float dv = t[k] - mu; vs += dv * dv; }
    float var = block_sum(vs, red) * (1.f / 1024.f);
    float inv = rsqrtf(var + 1e-3f);
#pragma unroll
    for (int k = 0; k < 4; k++) {
        const int d = tid + k * 256;
        float y = (t[k] - mu) * inv * g1[d] + b1[d];
        t[k] = y + cond[bb * Dc + d];
    }
    s = 0.f;
#pragma unroll
    for (int k = 0; k < 4; k++) s += t[k];
    mu = block_sum(s, red) * (1.f / 1024.f);
    vs = 0.f;
#pragma unroll
    for (int k = 0; k < 4; k++) { float dv = t[k] - mu; vs += dv * dv; }
    var = block_sum(vs, red) * (1.f / 1024.f);
    inv = rsqrtf(var + 1e-3f);
#pragma unroll
    for (int k = 0; k < 4; k++) {
        const int d = tid + k * 256;
        out2[(size_t)row * Dc + d] = (t[k] - mu) * inv * g2[d] + b2[d];
    }
}

// out = LN3(a + f)
__global__ void __launch_bounds__(256) ln3_kernel(
    const float* __restrict__ a, const float* __restrict__ f,
    const float* __restrict__ g3, const float* __restrict__ b3,
    float* __restrict__ out)
{
    __shared__ float red[8];
    const int row = blockIdx.x;
    const int tid = threadIdx.x;
    const float* ar = a + (size_t)row * Dc;
    const float* fr = f + (size_t)row * Dc;
    float t[4];
    float s = 0.f;
#pragma unroll
    for (int k = 0; k < 4; k++) {
        const int d = tid + k * 256;
        t[k] = ar[d] + fr[d];
        s += t[k];
    }
    float mu = block_sum(s, red) * (1.f / 1024.f);
    float vs = 0.f;
#pragma unroll
    for (int k = 0; k < 4; k++) { float dv = t[k] - mu; vs += dv * dv; }
    float var = block_sum(vs, red) * (1.f / 1024.f);
    float inv = rsqrtf(var + 1e-3f);
#pragma unroll
    for (int k = 0; k < 4; k++) {
        const int d = tid + k * 256;
        out[(size_t)row * Dc + d] = (t[k] - mu) * inv * g3[d] + b3[d];
    }
}

// ---------------- launch ----------------
extern "C" void kernel_launch(void* const* d_in, const int* in_sizes, int n_in,
                              void* d_out, int out_size) {
    const float* x    = (const float*)d_in[0];
    const float* z    = (const float*)d_in[1];
    const float* cond = (const float*)d_in[2];
    const int*   xm   = (const int*)  d_in[3];
    const float* WQ   = (const float*)d_in[4];
    const float* WK   = (const float*)d_in[5];
    const float* WV   = (const float*)d_in[6];
    const float* W1   = (const float*)d_in[7];
    const float* b1   = (const float*)d_in[8];
    const float* W2   = (const float*)d_in[9];
    const float* b2   = (const float*)d_in[10];
    const float* g1   = (const float*)d_in[11];
    const float* be1  = (const float*)d_in[12];
    const float* g2   = (const float*)d_in[13];
    const float* be2  = (const float*)d_in[14];
    const float* g3   = (const float*)d_in[15];
    const float* be3  = (const float*)d_in[16];
    float* out = (float*)d_out;

    float *pQ, *pK, *pV, *pO, *pO2, *pH, *pF;
    cudaGetSymbolAddress((void**)&pQ,  g_Q);
    cudaGetSymbolAddress((void**)&pK,  g_K);
    cudaGetSymbolAddress((void**)&pV,  g_V);
    cudaGetSymbolAddress((void**)&pO,  g_O);
    cudaGetSymbolAddress((void**)&pO2, g_O2);
    cudaGetSymbolAddress((void**)&pH,  g_H);
    cudaGetSymbolAddress((void**)&pF,  g_F);

    const dim3 gqkv(Dc / 128, Mrows / 128);
    gemm_kernel<0, false, false><<<gqkv, 256>>>(x, nullptr, WQ, nullptr, pQ, Mrows, Dc, Dc);
    gemm_kernel<0, false, false><<<gqkv, 256>>>(x, nullptr, WK, nullptr, pK, Mrows, Dc, Dc);
    gemm_kernel<0, false, false><<<gqkv, 256>>>(x, nullptr, WV, nullptr, pV, Mrows, Dc, Dc);

    attn_kernel<<<dim3(Sc / 64, Hc, Bc), 256>>>(pQ, pK, pV, xm, pO);

    ln12_kernel<<<Mrows, 256>>>(x, pO, cond, g1, be1, g2, be2, pO2);

    gemm_kernel<1, true, true><<<dim3(DFFc / 128, Mrows / 128), 256>>>(
        pO2, z, W1, b1, pH, Mrows, DFFc, Dc + DLATc);
    gemm_kernel<0, false, true><<<dim3(Dc / 128, Mrows / 128), 256>>>(
        pH, nullptr, W2, b2, pF, Mrows, Dc, DFFc);

    ln3_kernel<<<Mrows, 256>>>(pO2, pF, g3, be3, out);
}

// round 4
// speedup vs baseline: 1.4250x; 1.4250x over previous
#include <cuda_runtime.h>
#include <cstdint>

#define Bc   4
#define Sc   1024
#define Dc   1024
#define Hc   16
#define DHc  64
#define DFFc 4096
#define DLATc 256
#define Mrows (Bc * Sc)   // 4096

// ---------------- scratch (no cudaMalloc allowed) ----------------
__device__ float g_Q  [Bc * Sc * Dc];
__device__ float g_K  [Bc * Sc * Dc];
__device__ float g_V  [Bc * Sc * Dc];
__device__ float g_O  [Bc * Sc * Dc];
__device__ float g_O2 [Bc * Sc * Dc];
__device__ float g_H  [Bc * Sc * DFFc];
__device__ float g_F  [Bc * Sc * Dc];

// ---------------- small PTX helpers (base ISA only — no sm_100a features) ----
__device__ __forceinline__ uint32_t f2tf32(float f) {
    uint32_t u;
    asm("cvt.rna.tf32.f32 %0, %1;" : "=r"(u) : "f"(f));
    return u;
}
__device__ __forceinline__ void mma_tf32_16x8x8(
    float& c0, float& c1, float& c2, float& c3,
    uint32_t a0, uint32_t a1, uint32_t a2, uint32_t a3,
    uint32_t b0, uint32_t b1)
{
    asm volatile(
        "mma.sync.aligned.m16n8k8.row.col.f32.tf32.tf32.f32 "
        "{%0,%1,%2,%3}, {%4,%5,%6,%7}, {%8,%9}, {%0,%1,%2,%3};"
        : "+f"(c0), "+f"(c1), "+f"(c2), "+f"(c3)
        : "r"(a0), "r"(a1), "r"(a2), "r"(a3), "r"(b0), "r"(b1));
}
__device__ __forceinline__ uint32_t smem_to_u32(const void* p) {
    uint32_t a;
    asm("{ .reg .u64 t; cvta.to.shared.u64 t, %1; cvt.u32.u64 %0, t; }" : "=r"(a) : "l"(p));
    return a;
}
#define CP_ASYNC16(dst, src) \
    asm volatile("cp.async.cg.shared.global [%0], [%1], 16;" :: "r"(dst), "l"(src))
#define CP_COMMIT() asm volatile("cp.async.commit_group;" ::: "memory")
#define CP_WAIT1()  asm volatile("cp.async.wait_group 1;" ::: "memory")
#define CP_WAIT0()  asm volatile("cp.async.wait_group 0;" ::: "memory")

// ---------------- tf32 mma.sync GEMM ----------------
// C[M,N] = act(A @ W + bias); A [M,K] row-major (AMODE1: concat(A[1024], Z[256]));
// W [K,N] row-major (native layout — no transpose needed).
// CTA tile 128x128, K-chunk 32. 8 warps (2x4), warp tile 64x32 of m16n8k8.
#define AS_STRIDE 36    // A smem: [128][36] floats  (bank = 4r+c: conflict-free frags)
#define BS_STRIDE 136   // B smem: [32][136] floats  (bank = 8k+n: conflict-free frags)
#define AS_FLOATS (128 * AS_STRIDE)             // 4608
#define BS_FLOATS (32 * BS_STRIDE)              // 4352
#define BUF_FLOATS (AS_FLOATS + BS_FLOATS)      // 8960
#define GEMM_SMEM_BYTES (2 * BUF_FLOATS * 4)    // 71680

template<int AMODE>
__global__ void __launch_bounds__(256) mma_gemm(
    const float* __restrict__ A, const float* __restrict__ Z,
    const float* __restrict__ W, const float* __restrict__ bias,
    float* __restrict__ C, int N, int K, int relu)
{
    extern __shared__ float smem[];
    const uint32_t sb = smem_to_u32(smem);
    const int tid  = threadIdx.x;
    const int wid  = tid >> 5, lane = tid & 31;
    const int wm   = wid >> 2, wn = wid & 3;          // warp grid 2x4
    const int qrow = lane >> 2, qcol = lane & 3;      // quad row / col
    const int row0 = blockIdx.y * 128, col0 = blockIdx.x * 128;

    float acc[4][4][4];
#pragma unroll
    for (int i = 0; i < 4; i++)
#pragma unroll
        for (int j = 0; j < 4; j++)
#pragma unroll
            for (int r = 0; r < 4; r++) acc[i][j][r] = 0.f;

    const int NC = K / 32;

    // A: 128 rows x 32 k = 1024 float4; B: 32 k x 128 n = 1024 float4.
#define LOAD_CHUNK(c, s) do {                                                        \
    const int _k0 = (c) * 32;                                                        \
    const uint32_t _ab = sb + (uint32_t)((s) * BUF_FLOATS) * 4u;                     \
    const uint32_t _bb = _ab + AS_FLOATS * 4u;                                       \
    _Pragma("unroll")                                                                \
    for (int _u = tid; _u < 1024; _u += 256) {                                       \
        { /* A */                                                                    \
            const int _r = _u >> 3, _cc = _u & 7;                                    \
            const float* _as;                                                        \
            if (AMODE == 0) {                                                        \
                _as = A + (size_t)(row0 + _r) * K + _k0 + _cc * 4;                   \
            } else {                                                                 \
                const int _kc = _k0 + _cc * 4;                                       \
                if (_kc < Dc) _as = A + (size_t)(row0 + _r) * Dc + _kc;              \
                else _as = Z + (size_t)((row0 + _r) >> 10) * DLATc + (_kc - Dc);     \
            }                                                                        \
            CP_ASYNC16(_ab + (uint32_t)(_r * AS_STRIDE + _cc * 4) * 4u, _as);        \
        }                                                                            \
        { /* B */                                                                    \
            const int _r = _u >> 5, _cc = _u & 31;                                   \
            const float* _bs = W + (size_t)(_k0 + _r) * N + col0 + _cc * 4;          \
            CP_ASYNC16(_bb + (uint32_t)(_r * BS_STRIDE + _cc * 4) * 4u, _bs);        \
        }                                                                            \
    }                                                                                \
    CP_COMMIT();                                                                     \
} while (0)

    LOAD_CHUNK(0, 0);
    for (int c = 0; c < NC; c++) {
        const int s = c & 1;
        if (c + 1 < NC) { LOAD_CHUNK(c + 1, s ^ 1); CP_WAIT1(); }
        else            { CP_WAIT0(); }
        __syncthreads();

        const float* As = smem + s * BUF_FLOATS;
        const float* Bs = As + AS_FLOATS;
#pragma unroll
        for (int ks = 0; ks < 4; ks++) {
            const int k = ks * 8;
            uint32_t af[4][4];
#pragma unroll
            for (int mt = 0; mt < 4; mt++) {
                const int r = wm * 64 + mt * 16 + qrow;
                af[mt][0] = f2tf32(As[r * AS_STRIDE + k + qcol]);
                af[mt][1] = f2tf32(As[(r + 8) * AS_STRIDE + k + qcol]);
                af[mt][2] = f2tf32(As[r * AS_STRIDE + k + qcol + 4]);
                af[mt][3] = f2tf32(As[(r + 8) * AS_STRIDE + k + qcol + 4]);
            }
            uint32_t bf[4][2];
#pragma unroll
            for (int nt = 0; nt < 4; nt++) {
                const int n = wn * 32 + nt * 8 + qrow;
                bf[nt][0] = f2tf32(Bs[(k + qcol) * BS_STRIDE + n]);
                bf[nt][1] = f2tf32(Bs[(k + qcol + 4) * BS_STRIDE + n]);
            }
#pragma unroll
            for (int mt = 0; mt < 4; mt++)
#pragma unroll
                for (int nt = 0; nt < 4; nt++)
                    mma_tf32_16x8x8(acc[mt][nt][0], acc[mt][nt][1],
                                    acc[mt][nt][2], acc[mt][nt][3],
                                    af[mt][0], af[mt][1], af[mt][2], af[mt][3],
                                    bf[nt][0], bf[nt][1]);
        }
        __syncthreads();
    }

    // epilogue: c0,c1 at (row, 2q..2q+1), c2,c3 at (row+8, same cols)
#pragma unroll
    for (int mt = 0; mt < 4; mt++) {
        const int r = row0 + wm * 64 + mt * 16 + qrow;
#pragma unroll
        for (int nt = 0; nt < 4; nt++) {
            const int cc = col0 + wn * 32 + nt * 8 + 2 * qcol;
            float2 v0, v1;
            v0.x = acc[mt][nt][0]; v0.y = acc[mt][nt][1];
            v1.x = acc[mt][nt][2]; v1.y = acc[mt][nt][3];
            if (bias) {
                const float bx = bias[cc], by = bias[cc + 1];
                v0.x += bx; v0.y += by; v1.x += bx; v1.y += by;
            }
            if (relu) {
                v0.x = fmaxf(v0.x, 0.f); v0.y = fmaxf(v0.y, 0.f);
                v1.x = fmaxf(v1.x, 0.f); v1.y = fmaxf(v1.y, 0.f);
            }
            *(float2*)(C + (size_t)r * N + cc)       = v0;
            *(float2*)(C + (size_t)(r + 8) * N + cc) = v1;
        }
    }
}

// ---------------- flash attention (fp32, causal + key padding mask) ----------------
__global__ void __launch_bounds__(256) attn_kernel(
    const float* __restrict__ Q, const float* __restrict__ K,
    const float* __restrict__ V, const int* __restrict__ mask,
    float* __restrict__ O)
{
    __shared__ float Ks[64][68];
    __shared__ float Vs[64][68];
    __shared__ int   km[64];
    const int qt = blockIdx.x, h = blockIdx.y, b = blockIdx.z;
    const int q0 = qt * 64;
    const int tid = threadIdx.x;
    const int q = tid >> 2, g = tid & 3;
    const int lane_base = ((q & 7) << 2);
    const size_t base = ((size_t)b * Sc) * Dc + (size_t)h * DHc;

    float qreg[64];
    {
        const float* qp = Q + base + (size_t)(q0 + q) * Dc;
#pragma unroll
        for (int c = 0; c < 64; c += 4) {
            float4 v4 = *(const float4*)(qp + c);
            qreg[c] = v4.x; qreg[c + 1] = v4.y; qreg[c + 2] = v4.z; qreg[c + 3] = v4.w;
        }
    }
    const int mq = mask[b * Sc + q0 + q];

    float m = -1e30f, l = 0.f;
    float acc[16];
#pragma unroll
    for (int i = 0; i < 16; i++) acc[i] = 0.f;

    for (int kt = 0; kt <= qt; kt++) {
        const int k0 = kt * 64;
        __syncthreads();
        for (int i = tid; i < 64 * 16; i += 256) {
            const int r = i >> 4, c = (i & 15) << 2;
            *(float4*)(&Ks[r][c]) = *(const float4*)(K + base + (size_t)(k0 + r) * Dc + c);
            *(float4*)(&Vs[r][c]) = *(const float4*)(V + base + (size_t)(k0 + r) * Dc + c);
        }
        if (tid < 64) km[tid] = mask[b * Sc + k0 + tid];
        __syncthreads();

        float sv[16];
#pragma unroll
        for (int j = 0; j < 16; j++) sv[j] = 0.f;
#pragma unroll
        for (int dd = 0; dd < 64; dd += 4) {
#pragma unroll
            for (int j = 0; j < 16; j++) {
                float4 kv = *(const float4*)(&Ks[g * 16 + j][dd]);
                sv[j] += qreg[dd] * kv.x + qreg[dd + 1] * kv.y
                       + qreg[dd + 2] * kv.z + qreg[dd + 3] * kv.w;
            }
        }
        float mt = -1e30f;
#pragma unroll
        for (int j = 0; j < 16; j++) {
            const int kk = g * 16 + j;
            float s = sv[j] * 0.125f;
            if ((k0 + kk) > (q0 + q) || km[kk] == 0) s = -1e30f;
            sv[j] = s;
            mt = fmaxf(mt, s);
        }
        mt = fmaxf(mt, __shfl_xor_sync(0xffffffffu, mt, 1));
        mt = fmaxf(mt, __shfl_xor_sync(0xffffffffu, mt, 2));
        const float mnew  = fmaxf(m, mt);
        const float scale = __expf(m - mnew);
        float lt = 0.f;
#pragma unroll
        for (int j = 0; j < 16; j++) {
            sv[j] = __expf(sv[j] - mnew);
            lt += sv[j];
        }
        lt += __shfl_xor_sync(0xffffffffu, lt, 1);
        lt += __shfl_xor_sync(0xffffffffu, lt, 2);
        l = l * scale + lt;
        m = mnew;
#pragma unroll
        for (int i = 0; i < 16; i++) acc[i] *= scale;

#pragma unroll
        for (int kg = 0; kg < 4; kg++) {
#pragma unroll
            for (int j = 0; j < 16; j++) {
                const int k = kg * 16 + j;
                const float p = __shfl_sync(0xffffffffu, sv[j], lane_base + kg, 32);
                const float4 v0 = *(const float4*)(&Vs[k][g * 16 + 0]);
                const float4 v1 = *(const float4*)(&Vs[k][g * 16 + 4]);
                const float4 v2 = *(const float4*)(&Vs[k][g * 16 + 8]);
                const float4 v3 = *(const float4*)(&Vs[k][g * 16 + 12]);
                acc[0]  += p * v0.x; acc[1]  += p * v0.y; acc[2]  += p * v0.z; acc[3]  += p * v0.w;
                acc[4]  += p * v1.x; acc[5]  += p * v1.y; acc[6]  += p * v1.z; acc[7]  += p * v1.w;
                acc[8]  += p * v2.x; acc[9]  += p * v2.y; acc[10] += p * v2.z; acc[11] += p * v2.w;
                acc[12] += p * v3.x; acc[13] += p * v3.y; acc[14] += p * v3.z; acc[15] += p * v3.w;
            }
        }
    }

    const float inv = (mq != 0) ? (1.0f / l) : 0.f;
    float* op = O + base + (size_t)(q0 + q) * Dc + g * 16;
#pragma unroll
    for (int i = 0; i < 16; i += 4) {
        float4 v;
        v.x = acc[i] * inv; v.y = acc[i + 1] * inv;
        v.z = acc[i + 2] * inv; v.w = acc[i + 3] * inv;
        *(float4*)(op + i) = v;
    }
}

// ---------------- layernorm ----------------
__device__ __forceinline__ float block_sum(float v, float* red) {
#pragma unroll
    for (int o = 16; o > 0; o >>= 1) v += __shfl_xor_sync(0xffffffffu, v, o);
    const int lane = threadIdx.x & 31, w = threadIdx.x >> 5;
    __syncthreads();
    if (lane == 0) red[w] = v;
    __syncthreads();
    float s = 0.f;
#pragma unroll
    for (int i = 0; i < 8; i++) s += red[i];
    return s;
}

__global__ void __launch_bounds__(256) ln12_kernel(
    const float* __restrict__ x, const float* __restrict__ o,
    const float* __restrict__ cond,
    const float* __restrict__ g1, const float* __restrict__ b1,
    const float* __restrict__ g2, const float* __restrict__ b2,
    float* __restrict__ out2)
{
    __shared__ float red[8];
    const int row = blockIdx.x;
    const int bb  = row >> 10;
    const int tid = threadIdx.x;
    const float* xr = x + (size_t)row * Dc;
    const float* orr = o + (size_t)row * Dc;
    float t[4];
    float s = 0.f;
#pragma unroll
    for (int k = 0; k < 4; k++) {
        const int d = tid + k * 256;
        t[k] = xr[d] + orr[d];
        s += t[k];
    }
    float mu = block_sum(s, red) * (1.f / 1024.f);
    float vs = 0.f;
#pragma unroll
    for (int k = 0; k < 4; k++) { float dv = t[k] - mu; vs += dv * dv; }
    float var = block_sum(vs, red) * (1.f / 1024.f);
    float inv = rsqrtf(var + 1e-3f);
#pragma unroll
    for (int k = 0; k < 4; k++) {
        const int d = tid + k * 256;
        float y = (t[k] - mu) * inv * g1[d] + b1[d];
        t[k] = y + cond[bb * Dc + d];
    }
    s = 0.f;
#pragma unroll
    for (int k = 0; k < 4; k++) s += t[k];
    mu = block_sum(s, red) * (1.f / 1024.f);
    vs = 0.f;
#pragma unroll
    for (int k = 0; k < 4; k++) { float dv = t[k] - mu; vs += dv * dv; }
    var = block_sum(vs, red) * (1.f / 1024.f);
    inv = rsqrtf(var + 1e-3f);
#pragma unroll
    for (int k = 0; k < 4; k++) {
        const int d = tid + k * 256;
        out2[(size_t)row * Dc + d] = (t[k] - mu) * inv * g2[d] + b2[d];
    }
}

__global__ void __launch_bounds__(256) ln3_kernel(
    const float* __restrict__ a, const float* __restrict__ f,
    const float* __restrict__ g3, const float* __restrict__ b3,
    float* __restrict__ out)
{
    __shared__ float red[8];
    const int row = blockIdx.x;
    const int tid = threadIdx.x;
    const float* ar = a + (size_t)row * Dc;
    const float* fr = f + (size_t)row * Dc;
    float t[4];
    float s = 0.f;
#pragma unroll
    for (int k = 0; k < 4; k++) {
        const int d = tid + k * 256;
        t[k] = ar[d] + fr[d];
        s += t[k];
    }
    float mu = block_sum(s, red) * (1.f / 1024.f);
    float vs = 0.f;
#pragma unroll
    for (int k = 0; k < 4; k++) { float dv = t[k] - mu; vs += dv * dv; }
    float var = block_sum(vs, red) * (1.f / 1024.f);
    float inv = rsqrtf(var + 1e-3f);
#pragma unroll
    for (int k = 0; k < 4; k++) {
        const int d = tid + k * 256;
        out[(size_t)row * Dc + d] = (t[k] - mu) * inv * g3[d] + b3[d];
    }
}

// ---------------- launch ----------------
extern "C" void kernel_launch(void* const* d_in, const int* in_sizes, int n_in,
                              void* d_out, int out_size) {
    const float* x    = (const float*)d_in[0];
    const float* z    = (const float*)d_in[1];
    const float* cond = (const float*)d_in[2];
    const int*   xm   = (const int*)  d_in[3];
    const float* WQ   = (const float*)d_in[4];
    const float* WK   = (const float*)d_in[5];
    const float* WV   = (const float*)d_in[6];
    const float* W1   = (const float*)d_in[7];
    const float* b1   = (const float*)d_in[8];
    const float* W2   = (const float*)d_in[9];
    const float* b2   = (const float*)d_in[10];
    const float* g1   = (const float*)d_in[11];
    const float* be1  = (const float*)d_in[12];
    const float* g2   = (const float*)d_in[13];
    const float* be2  = (const float*)d_in[14];
    const float* g3   = (const float*)d_in[15];
    const float* be3  = (const float*)d_in[16];
    float* out = (float*)d_out;

    float *pQ, *pK, *pV, *pO, *pO2, *pH, *pF;
    cudaGetSymbolAddress((void**)&pQ,  g_Q);
    cudaGetSymbolAddress((void**)&pK,  g_K);
    cudaGetSymbolAddress((void**)&pV,  g_V);
    cudaGetSymbolAddress((void**)&pO,  g_O);
    cudaGetSymbolAddress((void**)&pO2, g_O2);
    cudaGetSymbolAddress((void**)&pH,  g_H);
    cudaGetSymbolAddress((void**)&pF,  g_F);

    // unconditional (no static guards per harness rules); host-side, capture-legal
    cudaFuncSetAttribute(mma_gemm<0>, cudaFuncAttributeMaxDynamicSharedMemorySize,
                         GEMM_SMEM_BYTES);
    cudaFuncSetAttribute(mma_gemm<1>, cudaFuncAttributeMaxDynamicSharedMemorySize,
                         GEMM_SMEM_BYTES);

    // QKV projections (W in native [K,N] layout — no transpose pass)
    mma_gemm<0><<<dim3(Dc / 128, Mrows / 128), 256, GEMM_SMEM_BYTES>>>(
        x, nullptr, WQ, nullptr, pQ, Dc, Dc, 0);
    mma_gemm<0><<<dim3(Dc / 128, Mrows / 128), 256, GEMM_SMEM_BYTES>>>(
        x, nullptr, WK, nullptr, pK, Dc, Dc, 0);
    mma_gemm<0><<<dim3(Dc / 128, Mrows / 128), 256, GEMM_SMEM_BYTES>>>(
        x, nullptr, WV, nullptr, pV, Dc, Dc, 0);

    attn_kernel<<<dim3(Sc / 64, Hc, Bc), 256>>>(pQ, pK, pV, xm, pO);

    ln12_kernel<<<Mrows, 256>>>(x, pO, cond, g1, be1, g2, be2, pO2);

    mma_gemm<1><<<dim3(DFFc / 128, Mrows / 128), 256, GEMM_SMEM_BYTES>>>(
        pO2, z, W1, b1, pH, DFFc, Dc + DLATc, 1);
    mma_gemm<0><<<dim3(Dc / 128, Mrows / 128), 256, GEMM_SMEM_BYTES>>>(
        pH, nullptr, W2, b2, pF, Dc, DFFc, 0);

    ln3_kernel<<<Mrows, 256>>>(pO2, pF, g3, be3, out);
}

// round 5
// speedup vs baseline: 3.5685x; 2.5042x over previous
#include <cuda_runtime.h>
#include <cstdint>

#define Bc   4
#define Sc   1024
#define Dc   1024
#define Hc   16
#define DHc  64
#define DFFc 4096
#define DLATc 256
#define Mrows (Bc * Sc)   // 4096

// ---------------- scratch (no cudaMalloc allowed) ----------------
__device__ float g_Q  [Bc * Sc * Dc];
__device__ float g_K  [Bc * Sc * Dc];
__device__ float g_V  [Bc * Sc * Dc];
__device__ float g_O  [Bc * Sc * Dc];
__device__ float g_O2 [Bc * Sc * Dc];
__device__ float g_H  [Bc * Sc * DFFc];
__device__ float g_F  [Bc * Sc * Dc];

// ---------------- small PTX helpers (base ISA only) ----------------
__device__ __forceinline__ uint32_t f2tf32(float f) {
    uint32_t u;
    asm("cvt.rna.tf32.f32 %0, %1;" : "=r"(u) : "f"(f));
    return u;
}
__device__ __forceinline__ void mma_tf32_16x8x8(
    float& c0, float& c1, float& c2, float& c3,
    uint32_t a0, uint32_t a1, uint32_t a2, uint32_t a3,
    uint32_t b0, uint32_t b1)
{
    asm volatile(
        "mma.sync.aligned.m16n8k8.row.col.f32.tf32.tf32.f32 "
        "{%0,%1,%2,%3}, {%4,%5,%6,%7}, {%8,%9}, {%0,%1,%2,%3};"
        : "+f"(c0), "+f"(c1), "+f"(c2), "+f"(c3)
        : "r"(a0), "r"(a1), "r"(a2), "r"(a3), "r"(b0), "r"(b1));
}
__device__ __forceinline__ uint32_t smem_to_u32(const void* p) {
    uint32_t a;
    asm("{ .reg .u64 t; cvta.to.shared.u64 t, %1; cvt.u32.u64 %0, t; }" : "=r"(a) : "l"(p));
    return a;
}
#define CP_ASYNC16(dst, src) \
    asm volatile("cp.async.cg.shared.global [%0], [%1], 16;" :: "r"(dst), "l"(src))
#define CP_COMMIT() asm volatile("cp.async.commit_group;" ::: "memory")
#define CP_WAIT1()  asm volatile("cp.async.wait_group 1;" ::: "memory")
#define CP_WAIT0()  asm volatile("cp.async.wait_group 0;" ::: "memory")

// ---------------- tf32 mma.sync GEMM (unchanged from R4) ----------------
#define AS_STRIDE 36
#define BS_STRIDE 136
#define AS_FLOATS (128 * AS_STRIDE)
#define BS_FLOATS (32 * BS_STRIDE)
#define BUF_FLOATS (AS_FLOATS + BS_FLOATS)
#define GEMM_SMEM_BYTES (2 * BUF_FLOATS * 4)

template<int AMODE>
__global__ void __launch_bounds__(256) mma_gemm(
    const float* __restrict__ A, const float* __restrict__ Z,
    const float* __restrict__ W, const float* __restrict__ bias,
    float* __restrict__ C, int N, int K, int relu)
{
    extern __shared__ float smem[];
    const uint32_t sb = smem_to_u32(smem);
    const int tid  = threadIdx.x;
    const int wid  = tid >> 5, lane = tid & 31;
    const int wm   = wid >> 2, wn = wid & 3;
    const int qrow = lane >> 2, qcol = lane & 3;
    const int row0 = blockIdx.y * 128, col0 = blockIdx.x * 128;

    float acc[4][4][4];
#pragma unroll
    for (int i = 0; i < 4; i++)
#pragma unroll
        for (int j = 0; j < 4; j++)
#pragma unroll
            for (int r = 0; r < 4; r++) acc[i][j][r] = 0.f;

    const int NC = K / 32;

#define LOAD_CHUNK(c, s) do {                                                        \
    const int _k0 = (c) * 32;                                                        \
    const uint32_t _ab = sb + (uint32_t)((s) * BUF_FLOATS) * 4u;                     \
    const uint32_t _bb = _ab + AS_FLOATS * 4u;                                       \
    _Pragma("unroll")                                                                \
    for (int _u = tid; _u < 1024; _u += 256) {                                       \
        {                                                                            \
            const int _r = _u >> 3, _cc = _u & 7;                                    \
            const float* _as;                                                        \
            if (AMODE == 0) {                                                        \
                _as = A + (size_t)(row0 + _r) * K + _k0 + _cc * 4;                   \
            } else {                                                                 \
                const int _kc = _k0 + _cc * 4;                                       \
                if (_kc < Dc) _as = A + (size_t)(row0 + _r) * Dc + _kc;              \
                else _as = Z + (size_t)((row0 + _r) >> 10) * DLATc + (_kc - Dc);     \
            }                                                                        \
            CP_ASYNC16(_ab + (uint32_t)(_r * AS_STRIDE + _cc * 4) * 4u, _as);        \
        }                                                                            \
        {                                                                            \
            const int _r = _u >> 5, _cc = _u & 31;                                   \
            const float* _bs = W + (size_t)(_k0 + _r) * N + col0 + _cc * 4;          \
            CP_ASYNC16(_bb + (uint32_t)(_r * BS_STRIDE + _cc * 4) * 4u, _bs);        \
        }                                                                            \
    }                                                                                \
    CP_COMMIT();                                                                     \
} while (0)

    LOAD_CHUNK(0, 0);
    for (int c = 0; c < NC; c++) {
        const int s = c & 1;
        if (c + 1 < NC) { LOAD_CHUNK(c + 1, s ^ 1); CP_WAIT1(); }
        else            { CP_WAIT0(); }
        __syncthreads();

        const float* As = smem + s * BUF_FLOATS;
        const float* Bs = As + AS_FLOATS;
#pragma unroll
        for (int ks = 0; ks < 4; ks++) {
            const int k = ks * 8;
            uint32_t af[4][4];
#pragma unroll
            for (int mt = 0; mt < 4; mt++) {
                const int r = wm * 64 + mt * 16 + qrow;
                af[mt][0] = f2tf32(As[r * AS_STRIDE + k + qcol]);
                af[mt][1] = f2tf32(As[(r + 8) * AS_STRIDE + k + qcol]);
                af[mt][2] = f2tf32(As[r * AS_STRIDE + k + qcol + 4]);
                af[mt][3] = f2tf32(As[(r + 8) * AS_STRIDE + k + qcol + 4]);
            }
            uint32_t bf[4][2];
#pragma unroll
            for (int nt = 0; nt < 4; nt++) {
                const int n = wn * 32 + nt * 8 + qrow;
                bf[nt][0] = f2tf32(Bs[(k + qcol) * BS_STRIDE + n]);
                bf[nt][1] = f2tf32(Bs[(k + qcol + 4) * BS_STRIDE + n]);
            }
#pragma unroll
            for (int mt = 0; mt < 4; mt++)
#pragma unroll
                for (int nt = 0; nt < 4; nt++)
                    mma_tf32_16x8x8(acc[mt][nt][0], acc[mt][nt][1],
                                    acc[mt][nt][2], acc[mt][nt][3],
                                    af[mt][0], af[mt][1], af[mt][2], af[mt][3],
                                    bf[nt][0], bf[nt][1]);
        }
        __syncthreads();
    }

#pragma unroll
    for (int mt = 0; mt < 4; mt++) {
        const int r = row0 + wm * 64 + mt * 16 + qrow;
#pragma unroll
        for (int nt = 0; nt < 4; nt++) {
            const int cc = col0 + wn * 32 + nt * 8 + 2 * qcol;
            float2 v0, v1;
            v0.x = acc[mt][nt][0]; v0.y = acc[mt][nt][1];
            v1.x = acc[mt][nt][2]; v1.y = acc[mt][nt][3];
            if (bias) {
                const float bx = bias[cc], by = bias[cc + 1];
                v0.x += bx; v0.y += by; v1.x += bx; v1.y += by;
            }
            if (relu) {
                v0.x = fmaxf(v0.x, 0.f); v0.y = fmaxf(v0.y, 0.f);
                v1.x = fmaxf(v1.x, 0.f); v1.y = fmaxf(v1.y, 0.f);
            }
            *(float2*)(C + (size_t)r * N + cc)       = v0;
            *(float2*)(C + (size_t)(r + 8) * N + cc) = v1;
        }
    }
}

// ---------------- tensor-core flash attention ----------------
// grid (S/64, H, B), 128 threads (4 warps). Warp w owns q-rows [w*16, w*16+16).
// Thread owns score/output rows {qrow, qrow+8} of the warp tile (m16n8 layout).
// KP buffer: K tile (stride 68) during QK, then P tile. Vs: stride 72 (72%32==8
// makes the PV b-frag pattern bank = 8*qcol+qrow, conflict-free, no transpose).
#define KP_STRIDE 68
#define V_STRIDE  72
__global__ void __launch_bounds__(128) attn_kernel(
    const float* __restrict__ Q, const float* __restrict__ K,
    const float* __restrict__ V, const int* __restrict__ mask,
    float* __restrict__ O)
{
    __shared__ float KP[64 * KP_STRIDE];
    __shared__ float Vs[64 * V_STRIDE];
    __shared__ int   km[64];
    const int qt = blockIdx.x, h = blockIdx.y, b = blockIdx.z;
    const int q0 = qt * 64;
    const int tid = threadIdx.x;
    const int w = tid >> 5, lane = tid & 31;
    const int qrow = lane >> 2, qcol = lane & 3;
    const size_t base = ((size_t)b * Sc) * Dc + (size_t)h * DHc;

    // stage Q tile through KP, build persistent A-fragments (pre-scaled 1/8)
    for (int i = tid; i < 64 * 16; i += 128) {
        const int r = i >> 4, c = (i & 15) << 2;
        *(float4*)(KP + r * KP_STRIDE + c) =
            *(const float4*)(Q + base + (size_t)(q0 + r) * Dc + c);
    }
    __syncthreads();
    uint32_t qf[8][4];
    {
        const int r0 = w * 16 + qrow;
#pragma unroll
        for (int ks = 0; ks < 8; ks++) {
            qf[ks][0] = f2tf32(KP[r0 * KP_STRIDE + ks * 8 + qcol] * 0.125f);
            qf[ks][1] = f2tf32(KP[(r0 + 8) * KP_STRIDE + ks * 8 + qcol] * 0.125f);
            qf[ks][2] = f2tf32(KP[r0 * KP_STRIDE + ks * 8 + qcol + 4] * 0.125f);
            qf[ks][3] = f2tf32(KP[(r0 + 8) * KP_STRIDE + ks * 8 + qcol + 4] * 0.125f);
        }
    }
    const int qg0 = q0 + w * 16 + qrow, qg1 = qg0 + 8;
    const int mq0 = mask[b * Sc + qg0], mq1 = mask[b * Sc + qg1];

    float m0 = -1e30f, m1 = -1e30f, l0 = 0.f, l1 = 0.f;
    float oacc[8][4];
#pragma unroll
    for (int nt = 0; nt < 8; nt++)
#pragma unroll
        for (int e = 0; e < 4; e++) oacc[nt][e] = 0.f;

    for (int kt = 0; kt <= qt; kt++) {
        const int k0 = kt * 64;
        __syncthreads();   // prior tile's KP(P)/Vs reads done; Q staging done
        // load K -> KP, V -> Vs (both tf32-converted once here)
        for (int i = tid; i < 64 * 16; i += 128) {
            const int r = i >> 4, c = (i & 15) << 2;
            float4 kv = *(const float4*)(K + base + (size_t)(k0 + r) * Dc + c);
            float* kd = KP + r * KP_STRIDE + c;
            kd[0] = __uint_as_float(f2tf32(kv.x));
            kd[1] = __uint_as_float(f2tf32(kv.y));
            kd[2] = __uint_as_float(f2tf32(kv.z));
            kd[3] = __uint_as_float(f2tf32(kv.w));
            float4 vv = *(const float4*)(V + base + (size_t)(k0 + r) * Dc + c);
            float* vd = Vs + r * V_STRIDE + c;
            vd[0] = __uint_as_float(f2tf32(vv.x));
            vd[1] = __uint_as_float(f2tf32(vv.y));
            vd[2] = __uint_as_float(f2tf32(vv.z));
            vd[3] = __uint_as_float(f2tf32(vv.w));
        }
        if (tid < 64) km[tid] = mask[b * Sc + k0 + tid];
        __syncthreads();

        // QK^T: b0 = K[key=8nt+qrow][dim=8ks+qcol]  (bank 4*qrow+qcol: clean)
        float sc[8][4];
#pragma unroll
        for (int nt = 0; nt < 8; nt++) {
            sc[nt][0] = sc[nt][1] = sc[nt][2] = sc[nt][3] = 0.f;
            const float* kr = KP + (nt * 8 + qrow) * KP_STRIDE;
#pragma unroll
            for (int ks = 0; ks < 8; ks++) {
                const uint32_t b0 = __float_as_uint(kr[ks * 8 + qcol]);
                const uint32_t b1 = __float_as_uint(kr[ks * 8 + qcol + 4]);
                mma_tf32_16x8x8(sc[nt][0], sc[nt][1], sc[nt][2], sc[nt][3],
                                qf[ks][0], qf[ks][1], qf[ks][2], qf[ks][3], b0, b1);
            }
        }
        // mask + row max (rows qrow / qrow+8; cols 2qcol, 2qcol+1 per nt)
        float mt0 = -1e30f, mt1 = -1e30f;
#pragma unroll
        for (int nt = 0; nt < 8; nt++) {
            const int kk0 = nt * 8 + 2 * qcol, kk1 = kk0 + 1;
            const int msk0 = km[kk0], msk1 = km[kk1];
            if ((k0 + kk0) > qg0 || msk0 == 0) sc[nt][0] = -1e30f;
            if ((k0 + kk1) > qg0 || msk1 == 0) sc[nt][1] = -1e30f;
            if ((k0 + kk0) > qg1 || msk0 == 0) sc[nt][2] = -1e30f;
            if ((k0 + kk1) > qg1 || msk1 == 0) sc[nt][3] = -1e30f;
            mt0 = fmaxf(mt0, fmaxf(sc[nt][0], sc[nt][1]));
            mt1 = fmaxf(mt1, fmaxf(sc[nt][2], sc[nt][3]));
        }
        mt0 = fmaxf(mt0, __shfl_xor_sync(0xffffffffu, mt0, 1));
        mt0 = fmaxf(mt0, __shfl_xor_sync(0xffffffffu, mt0, 2));
        mt1 = fmaxf(mt1, __shfl_xor_sync(0xffffffffu, mt1, 1));
        mt1 = fmaxf(mt1, __shfl_xor_sync(0xffffffffu, mt1, 2));
        const float mn0 = fmaxf(m0, mt0), mn1 = fmaxf(m1, mt1);
        const float sc0 = __expf(m0 - mn0), sc1 = __expf(m1 - mn1);
        float lt0 = 0.f, lt1 = 0.f;
#pragma unroll
        for (int nt = 0; nt < 8; nt++) {
            sc[nt][0] = __expf(sc[nt][0] - mn0);
            sc[nt][1] = __expf(sc[nt][1] - mn0);
            sc[nt][2] = __expf(sc[nt][2] - mn1);
            sc[nt][3] = __expf(sc[nt][3] - mn1);
            lt0 += sc[nt][0] + sc[nt][1];
            lt1 += sc[nt][2] + sc[nt][3];
        }
        lt0 += __shfl_xor_sync(0xffffffffu, lt0, 1);
        lt0 += __shfl_xor_sync(0xffffffffu, lt0, 2);
        lt1 += __shfl_xor_sync(0xffffffffu, lt1, 1);
        lt1 += __shfl_xor_sync(0xffffffffu, lt1, 2);
        l0 = l0 * sc0 + lt0; m0 = mn0;
        l1 = l1 * sc1 + lt1; m1 = mn1;
#pragma unroll
        for (int nt = 0; nt < 8; nt++) {
            oacc[nt][0] *= sc0; oacc[nt][1] *= sc0;
            oacc[nt][2] *= sc1; oacc[nt][3] *= sc1;
        }

        __syncthreads();   // everyone done reading K from KP
        // store P (tf32 bits) into KP rows [w*16, w*16+16) — warp-local
        {
            float* pr0 = KP + (w * 16 + qrow) * KP_STRIDE;
            float* pr1 = KP + (w * 16 + qrow + 8) * KP_STRIDE;
#pragma unroll
            for (int nt = 0; nt < 8; nt++) {
                const int cc = nt * 8 + 2 * qcol;
                float2 p0, p1;
                p0.x = __uint_as_float(f2tf32(sc[nt][0]));
                p0.y = __uint_as_float(f2tf32(sc[nt][1]));
                p1.x = __uint_as_float(f2tf32(sc[nt][2]));
                p1.y = __uint_as_float(f2tf32(sc[nt][3]));
                *(float2*)(pr0 + cc) = p0;
                *(float2*)(pr1 + cc) = p1;
            }
        }
        __syncwarp();
        // P A-fragments (bank 4*qrow+qcol: clean)
        uint32_t pf[8][4];
        {
            const int r0 = w * 16 + qrow;
#pragma unroll
            for (int ks = 0; ks < 8; ks++) {
                pf[ks][0] = __float_as_uint(KP[r0 * KP_STRIDE + ks * 8 + qcol]);
                pf[ks][1] = __float_as_uint(KP[(r0 + 8) * KP_STRIDE + ks * 8 + qcol]);
                pf[ks][2] = __float_as_uint(KP[r0 * KP_STRIDE + ks * 8 + qcol + 4]);
                pf[ks][3] = __float_as_uint(KP[(r0 + 8) * KP_STRIDE + ks * 8 + qcol + 4]);
            }
        }
        // PV: b0 = V[key=8ks+qcol][dim=8nt+qrow]  (stride 72 -> bank 8qcol+qrow: clean)
#pragma unroll
        for (int nt = 0; nt < 8; nt++) {
#pragma unroll
            for (int ks = 0; ks < 8; ks++) {
                const float* vr = Vs + (ks * 8 + qcol) * V_STRIDE + nt * 8 + qrow;
                const uint32_t b0 = __float_as_uint(vr[0]);
                const uint32_t b1 = __float_as_uint(*(vr + 4 * V_STRIDE));
                mma_tf32_16x8x8(oacc[nt][0], oacc[nt][1], oacc[nt][2], oacc[nt][3],
                                pf[ks][0], pf[ks][1], pf[ks][2], pf[ks][3], b0, b1);
            }
        }
    }

    const float inv0 = (mq0 != 0) ? (1.0f / l0) : 0.f;
    const float inv1 = (mq1 != 0) ? (1.0f / l1) : 0.f;
    float* o0 = O + base + (size_t)qg0 * Dc;
    float* o1 = O + base + (size_t)qg1 * Dc;
#pragma unroll
    for (int nt = 0; nt < 8; nt++) {
        const int cc = nt * 8 + 2 * qcol;
        float2 v0, v1;
        v0.x = oacc[nt][0] * inv0; v0.y = oacc[nt][1] * inv0;
        v1.x = oacc[nt][2] * inv1; v1.y = oacc[nt][3] * inv1;
        *(float2*)(o0 + cc) = v0;
        *(float2*)(o1 + cc) = v1;
    }
}

// ---------------- layernorm ----------------
__device__ __forceinline__ float block_sum(float v, float* red) {
#pragma unroll
    for (int o = 16; o > 0; o >>= 1) v += __shfl_xor_sync(0xffffffffu, v, o);
    const int lane = threadIdx.x & 31, w = threadIdx.x >> 5;
    __syncthreads();
    if (lane == 0) red[w] = v;
    __syncthreads();
    float s = 0.f;
#pragma unroll
    for (int i = 0; i < 8; i++) s += red[i];
    return s;
}

__global__ void __launch_bounds__(256) ln12_kernel(
    const float* __restrict__ x, const float* __restrict__ o,
    const float* __restrict__ cond,
    const float* __restrict__ g1, const float* __restrict__ b1,
    const float* __restrict__ g2, const float* __restrict__ b2,
    float* __restrict__ out2)
{
    __shared__ float red[8];
    const int row = blockIdx.x;
    const int bb  = row >> 10;
    const int tid = threadIdx.x;
    const float* xr = x + (size_t)row * Dc;
    const float* orr = o + (size_t)row * Dc;
    float t[4];
    float s = 0.f;
#pragma unroll
    for (int k = 0; k < 4; k++) {
        const int d = tid + k * 256;
        t[k] = xr[d] + orr[d];
        s += t[k];
    }
    float mu = block_sum(s, red) * (1.f / 1024.f);
    float vs = 0.f;
#pragma unroll
    for (int k = 0; k < 4; k++) { float dv = t[k] - mu; vs += dv * dv; }
    float var = block_sum(vs, red) * (1.f / 1024.f);
    float inv = rsqrtf(var + 1e-3f);
#pragma unroll
    for (int k = 0; k < 4; k++) {
        const int d = tid + k * 256;
        float y = (t[k] - mu) * inv * g1[d] + b1[d];
        t[k] = y + cond[bb * Dc + d];
    }
    s = 0.f;
#pragma unroll
    for (int k = 0; k < 4; k++) s += t[k];
    mu = block_sum(s, red) * (1.f / 1024.f);
    vs = 0.f;
#pragma unroll
    for (int k = 0; k < 4; k++) { float dv = t[k] - mu; vs += dv * dv; }
    var = block_sum(vs, red) * (1.f / 1024.f);
    inv = rsqrtf(var + 1e-3f);
#pragma unroll
    for (int k = 0; k < 4; k++) {
        const int d = tid + k * 256;
        out2[(size_t)row * Dc + d] = (t[k] - mu) * inv * g2[d] + b2[d];
    }
}

__global__ void __launch_bounds__(256) ln3_kernel(
    const float* __restrict__ a, const float* __restrict__ f,
    const float* __restrict__ g3, const float* __restrict__ b3,
    float* __restrict__ out)
{
    __shared__ float red[8];
    const int row = blockIdx.x;
    const int tid = threadIdx.x;
    const float* ar = a + (size_t)row * Dc;
    const float* fr = f + (size_t)row * Dc;
    float t[4];
    float s = 0.f;
#pragma unroll
    for (int k = 0; k < 4; k++) {
        const int d = tid + k * 256;
        t[k] = ar[d] + fr[d];
        s += t[k];
    }
    float mu = block_sum(s, red) * (1.f / 1024.f);
    float vs = 0.f;
#pragma unroll
    for (int k = 0; k < 4; k++) { float dv = t[k] - mu; vs += dv * dv; }
    float var = block_sum(vs, red) * (1.f / 1024.f);
    float inv = rsqrtf(var + 1e-3f);
#pragma unroll
    for (int k = 0; k < 4; k++) {
        const int d = tid + k * 256;
        out[(size_t)row * Dc + d] = (t[k] - mu) * inv * g3[d] + b3[d];
    }
}

// ---------------- launch ----------------
extern "C" void kernel_launch(void* const* d_in, const int* in_sizes, int n_in,
                              void* d_out, int out_size) {
    const float* x    = (const float*)d_in[0];
    const float* z    = (const float*)d_in[1];
    const float* cond = (const float*)d_in[2];
    const int*   xm   = (const int*)  d_in[3];
    const float* WQ   = (const float*)d_in[4];
    const float* WK   = (const float*)d_in[5];
    const float* WV   = (const float*)d_in[6];
    const float* W1   = (const float*)d_in[7];
    const float* b1   = (const float*)d_in[8];
    const float* W2   = (const float*)d_in[9];
    const float* b2   = (const float*)d_in[10];
    const float* g1   = (const float*)d_in[11];
    const float* be1  = (const float*)d_in[12];
    const float* g2   = (const float*)d_in[13];
    const float* be2  = (const float*)d_in[14];
    const float* g3   = (const float*)d_in[15];
    const float* be3  = (const float*)d_in[16];
    float* out = (float*)d_out;

    float *pQ, *pK, *pV, *pO, *pO2, *pH, *pF;
    cudaGetSymbolAddress((void**)&pQ,  g_Q);
    cudaGetSymbolAddress((void**)&pK,  g_K);
    cudaGetSymbolAddress((void**)&pV,  g_V);
    cudaGetSymbolAddress((void**)&pO,  g_O);
    cudaGetSymbolAddress((void**)&pO2, g_O2);
    cudaGetSymbolAddress((void**)&pH,  g_H);
    cudaGetSymbolAddress((void**)&pF,  g_F);

    cudaFuncSetAttribute(mma_gemm<0>, cudaFuncAttributeMaxDynamicSharedMemorySize,
                         GEMM_SMEM_BYTES);
    cudaFuncSetAttribute(mma_gemm<1>, cudaFuncAttributeMaxDynamicSharedMemorySize,
                         GEMM_SMEM_BYTES);

    mma_gemm<0><<<dim3(Dc / 128, Mrows / 128), 256, GEMM_SMEM_BYTES>>>(
        x, nullptr, WQ, nullptr, pQ, Dc, Dc, 0);
    mma_gemm<0><<<dim3(Dc / 128, Mrows / 128), 256, GEMM_SMEM_BYTES>>>(
        x, nullptr, WK, nullptr, pK, Dc, Dc, 0);
    mma_gemm<0><<<dim3(Dc / 128, Mrows / 128), 256, GEMM_SMEM_BYTES>>>(
        x, nullptr, WV, nullptr, pV, Dc, Dc, 0);

    attn_kernel<<<dim3(Sc / 64, Hc, Bc), 128>>>(pQ, pK, pV, xm, pO);

    ln12_kernel<<<Mrows, 256>>>(x, pO, cond, g1, be1, g2, be2, pO2);

    mma_gemm<1><<<dim3(DFFc / 128, Mrows / 128), 256, GEMM_SMEM_BYTES>>>(
        pO2, z, W1, b1, pH, DFFc, Dc + DLATc, 1);
    mma_gemm<0><<<dim3(Dc / 128, Mrows / 128), 256, GEMM_SMEM_BYTES>>>(
        pH, nullptr, W2, b2, pF, Dc, DFFc, 0);

    ln3_kernel<<<Mrows, 256>>>(pO2, pF, g3, be3, out);
}

// round 6
// speedup vs baseline: 3.8297x; 1.0732x over previous
#include <cuda_runtime.h>
#include <cstdint>

#define Bc   4
#define Sc   1024
#define Dc   1024
#define Hc   16
#define DHc  64
#define DFFc 4096
#define DLATc 256
#define Mrows (Bc * Sc)   // 4096

// ---------------- scratch (no cudaMalloc allowed) ----------------
__device__ float g_Q  [Bc * Sc * Dc];
__device__ float g_K  [Bc * Sc * Dc];
__device__ float g_V  [Bc * Sc * Dc];
__device__ float g_O  [Bc * Sc * Dc];
__device__ float g_O2 [Bc * Sc * Dc];
__device__ float g_H  [Bc * Sc * DFFc];
__device__ float g_F  [Bc * Sc * Dc];

// ---------------- small PTX helpers (base ISA only) ----------------
// tf32 MMA fed with RAW fp32 bits: HW uses the upper 19 bits (truncation).
__device__ __forceinline__ void mma_tf32_16x8x8(
    float& c0, float& c1, float& c2, float& c3,
    uint32_t a0, uint32_t a1, uint32_t a2, uint32_t a3,
    uint32_t b0, uint32_t b1)
{
    asm volatile(
        "mma.sync.aligned.m16n8k8.row.col.f32.tf32.tf32.f32 "
        "{%0,%1,%2,%3}, {%4,%5,%6,%7}, {%8,%9}, {%0,%1,%2,%3};"
        : "+f"(c0), "+f"(c1), "+f"(c2), "+f"(c3)
        : "r"(a0), "r"(a1), "r"(a2), "r"(a3), "r"(b0), "r"(b1));
}
__device__ __forceinline__ uint32_t smem_to_u32(const void* p) {
    uint32_t a;
    asm("{ .reg .u64 t; cvta.to.shared.u64 t, %1; cvt.u32.u64 %0, t; }" : "=r"(a) : "l"(p));
    return a;
}
#define CP_ASYNC16(dst, src) \
    asm volatile("cp.async.cg.shared.global [%0], [%1], 16;" :: "r"(dst), "l"(src))
#define CP_COMMIT() asm volatile("cp.async.commit_group;" ::: "memory")
#define CP_WAIT1()  asm volatile("cp.async.wait_group 1;" ::: "memory")
#define CP_WAIT0()  asm volatile("cp.async.wait_group 0;" ::: "memory")

// ---------------- tf32 mma.sync GEMM ----------------
// CTA tile 128x128, K-chunk 32. 4 warps (2x2), warp tile 64x64 of m16n8k8.
// Per chunk per warp: 128 LDS / 128 MMAs (no cvts).
#define AS_STRIDE 36
#define BS_STRIDE 136
#define AS_FLOATS (128 * AS_STRIDE)
#define BS_FLOATS (32 * BS_STRIDE)
#define BUF_FLOATS (AS_FLOATS + BS_FLOATS)
#define GEMM_SMEM_BYTES (2 * BUF_FLOATS * 4)

template<int AMODE>
__global__ void __launch_bounds__(128, 2) mma_gemm(
    const float* __restrict__ A, const float* __restrict__ Z,
    const float* __restrict__ W, const float* __restrict__ bias,
    float* __restrict__ C, int N, int K, int relu)
{
    extern __shared__ float smem[];
    const uint32_t sb = smem_to_u32(smem);
    const int tid  = threadIdx.x;
    const int wid  = tid >> 5, lane = tid & 31;
    const int wm   = wid >> 1, wn = wid & 1;          // warp grid 2x2
    const int qrow = lane >> 2, qcol = lane & 3;
    const int row0 = blockIdx.y * 128, col0 = blockIdx.x * 128;

    float acc[4][8][4];
#pragma unroll
    for (int i = 0; i < 4; i++)
#pragma unroll
        for (int j = 0; j < 8; j++)
#pragma unroll
            for (int r = 0; r < 4; r++) acc[i][j][r] = 0.f;

    const int NC = K / 32;

#define LOAD_CHUNK(c, s) do {                                                        \
    const int _k0 = (c) * 32;                                                        \
    const uint32_t _ab = sb + (uint32_t)((s) * BUF_FLOATS) * 4u;                     \
    const uint32_t _bb = _ab + AS_FLOATS * 4u;                                       \
    _Pragma("unroll")                                                                \
    for (int _u = tid; _u < 1024; _u += 128) {                                       \
        {                                                                            \
            const int _r = _u >> 3, _cc = _u & 7;                                    \
            const float* _as;                                                        \
            if (AMODE == 0) {                                                        \
                _as = A + (size_t)(row0 + _r) * K + _k0 + _cc * 4;                   \
            } else {                                                                 \
                const int _kc = _k0 + _cc * 4;                                       \
                if (_kc < Dc) _as = A + (size_t)(row0 + _r) * Dc + _kc;              \
                else _as = Z + (size_t)((row0 + _r) >> 10) * DLATc + (_kc - Dc);     \
            }                                                                        \
            CP_ASYNC16(_ab + (uint32_t)(_r * AS_STRIDE + _cc * 4) * 4u, _as);        \
        }                                                                            \
        {                                                                            \
            const int _r = _u >> 5, _cc = _u & 31;                                   \
            const float* _bs = W + (size_t)(_k0 + _r) * N + col0 + _cc * 4;          \
            CP_ASYNC16(_bb + (uint32_t)(_r * BS_STRIDE + _cc * 4) * 4u, _bs);        \
        }                                                                            \
    }                                                                                \
    CP_COMMIT();                                                                     \
} while (0)

    LOAD_CHUNK(0, 0);
    for (int c = 0; c < NC; c++) {
        const int s = c & 1;
        if (c + 1 < NC) { LOAD_CHUNK(c + 1, s ^ 1); CP_WAIT1(); }
        else            { CP_WAIT0(); }
        __syncthreads();

        const float* As = smem + s * BUF_FLOATS;
        const float* Bs = As + AS_FLOATS;
#pragma unroll
        for (int ks = 0; ks < 4; ks++) {
            const int k = ks * 8;
            uint32_t af[4][4];
#pragma unroll
            for (int mt = 0; mt < 4; mt++) {
                const int r = wm * 64 + mt * 16 + qrow;
                af[mt][0] = __float_as_uint(As[r * AS_STRIDE + k + qcol]);
                af[mt][1] = __float_as_uint(As[(r + 8) * AS_STRIDE + k + qcol]);
                af[mt][2] = __float_as_uint(As[r * AS_STRIDE + k + qcol + 4]);
                af[mt][3] = __float_as_uint(As[(r + 8) * AS_STRIDE + k + qcol + 4]);
            }
            uint32_t bf[8][2];
#pragma unroll
            for (int nt = 0; nt < 8; nt++) {
                const int n = wn * 64 + nt * 8 + qrow;
                bf[nt][0] = __float_as_uint(Bs[(k + qcol) * BS_STRIDE + n]);
                bf[nt][1] = __float_as_uint(Bs[(k + qcol + 4) * BS_STRIDE + n]);
            }
#pragma unroll
            for (int mt = 0; mt < 4; mt++)
#pragma unroll
                for (int nt = 0; nt < 8; nt++)
                    mma_tf32_16x8x8(acc[mt][nt][0], acc[mt][nt][1],
                                    acc[mt][nt][2], acc[mt][nt][3],
                                    af[mt][0], af[mt][1], af[mt][2], af[mt][3],
                                    bf[nt][0], bf[nt][1]);
        }
        __syncthreads();
    }

#pragma unroll
    for (int mt = 0; mt < 4; mt++) {
        const int r = row0 + wm * 64 + mt * 16 + qrow;
#pragma unroll
        for (int nt = 0; nt < 8; nt++) {
            const int cc = col0 + wn * 64 + nt * 8 + 2 * qcol;
            float2 v0, v1;
            v0.x = acc[mt][nt][0]; v0.y = acc[mt][nt][1];
            v1.x = acc[mt][nt][2]; v1.y = acc[mt][nt][3];
            if (bias) {
                const float bx = bias[cc], by = bias[cc + 1];
                v0.x += bx; v0.y += by; v1.x += bx; v1.y += by;
            }
            if (relu) {
                v0.x = fmaxf(v0.x, 0.f); v0.y = fmaxf(v0.y, 0.f);
                v1.x = fmaxf(v1.x, 0.f); v1.y = fmaxf(v1.y, 0.f);
            }
            *(float2*)(C + (size_t)r * N + cc)       = v0;
            *(float2*)(C + (size_t)(r + 8) * N + cc) = v1;
        }
    }
}

// ---------------- tensor-core flash attention ----------------
// grid (S/64, H, B), 128 threads (4 warps). Warp w owns q-rows [w*16, w*16+16).
// Raw fp32 bits fed to tf32 MMA everywhere (no cvts).
#define KP_STRIDE 68
#define V_STRIDE  72
__global__ void __launch_bounds__(128) attn_kernel(
    const float* __restrict__ Q, const float* __restrict__ K,
    const float* __restrict__ V, const int* __restrict__ mask,
    float* __restrict__ O)
{
    __shared__ float KP[64 * KP_STRIDE];
    __shared__ float Vs[64 * V_STRIDE];
    __shared__ int   km[64];
    const int qt = blockIdx.x, h = blockIdx.y, b = blockIdx.z;
    const int q0 = qt * 64;
    const int tid = threadIdx.x;
    const int w = tid >> 5, lane = tid & 31;
    const int qrow = lane >> 2, qcol = lane & 3;
    const size_t base = ((size_t)b * Sc) * Dc + (size_t)h * DHc;

    // stage Q tile through KP, build persistent A-fragments (pre-scaled 1/8)
    for (int i = tid; i < 64 * 16; i += 128) {
        const int r = i >> 4, c = (i & 15) << 2;
        *(float4*)(KP + r * KP_STRIDE + c) =
            *(const float4*)(Q + base + (size_t)(q0 + r) * Dc + c);
    }
    __syncthreads();
    uint32_t qf[8][4];
    {
        const int r0 = w * 16 + qrow;
#pragma unroll
        for (int ks = 0; ks < 8; ks++) {
            qf[ks][0] = __float_as_uint(KP[r0 * KP_STRIDE + ks * 8 + qcol] * 0.125f);
            qf[ks][1] = __float_as_uint(KP[(r0 + 8) * KP_STRIDE + ks * 8 + qcol] * 0.125f);
            qf[ks][2] = __float_as_uint(KP[r0 * KP_STRIDE + ks * 8 + qcol + 4] * 0.125f);
            qf[ks][3] = __float_as_uint(KP[(r0 + 8) * KP_STRIDE + ks * 8 + qcol + 4] * 0.125f);
        }
    }
    const int qg0 = q0 + w * 16 + qrow, qg1 = qg0 + 8;
    const int mq0 = mask[b * Sc + qg0], mq1 = mask[b * Sc + qg1];

    float m0 = -1e30f, m1 = -1e30f, l0 = 0.f, l1 = 0.f;
    float oacc[8][4];
#pragma unroll
    for (int nt = 0; nt < 8; nt++)
#pragma unroll
        for (int e = 0; e < 4; e++) oacc[nt][e] = 0.f;

    for (int kt = 0; kt <= qt; kt++) {
        const int k0 = kt * 64;
        __syncthreads();
        for (int i = tid; i < 64 * 16; i += 128) {
            const int r = i >> 4, c = (i & 15) << 2;
            *(float4*)(KP + r * KP_STRIDE + c) =
                *(const float4*)(K + base + (size_t)(k0 + r) * Dc + c);
            *(float4*)(Vs + r * V_STRIDE + c) =
                *(const float4*)(V + base + (size_t)(k0 + r) * Dc + c);
        }
        if (tid < 64) km[tid] = mask[b * Sc + k0 + tid];
        __syncthreads();

        float sc[8][4];
#pragma unroll
        for (int nt = 0; nt < 8; nt++) {
            sc[nt][0] = sc[nt][1] = sc[nt][2] = sc[nt][3] = 0.f;
            const float* kr = KP + (nt * 8 + qrow) * KP_STRIDE;
#pragma unroll
            for (int ks = 0; ks < 8; ks++) {
                const uint32_t b0 = __float_as_uint(kr[ks * 8 + qcol]);
                const uint32_t b1 = __float_as_uint(kr[ks * 8 + qcol + 4]);
                mma_tf32_16x8x8(sc[nt][0], sc[nt][1], sc[nt][2], sc[nt][3],
                                qf[ks][0], qf[ks][1], qf[ks][2], qf[ks][3], b0, b1);
            }
        }
        float mt0 = -1e30f, mt1 = -1e30f;
#pragma unroll
        for (int nt = 0; nt < 8; nt++) {
            const int kk0 = nt * 8 + 2 * qcol, kk1 = kk0 + 1;
            const int msk0 = km[kk0], msk1 = km[kk1];
            if ((k0 + kk0) > qg0 || msk0 == 0) sc[nt][0] = -1e30f;
            if ((k0 + kk1) > qg0 || msk1 == 0) sc[nt][1] = -1e30f;
            if ((k0 + kk0) > qg1 || msk0 == 0) sc[nt][2] = -1e30f;
            if ((k0 + kk1) > qg1 || msk1 == 0) sc[nt][3] = -1e30f;
            mt0 = fmaxf(mt0, fmaxf(sc[nt][0], sc[nt][1]));
            mt1 = fmaxf(mt1, fmaxf(sc[nt][2], sc[nt][3]));
        }
        mt0 = fmaxf(mt0, __shfl_xor_sync(0xffffffffu, mt0, 1));
        mt0 = fmaxf(mt0, __shfl_xor_sync(0xffffffffu, mt0, 2));
        mt1 = fmaxf(mt1, __shfl_xor_sync(0xffffffffu, mt1, 1));
        mt1 = fmaxf(mt1, __shfl_xor_sync(0xffffffffu, mt1, 2));
        const float mn0 = fmaxf(m0, mt0), mn1 = fmaxf(m1, mt1);
        const float sc0 = __expf(m0 - mn0), sc1 = __expf(m1 - mn1);
        float lt0 = 0.f, lt1 = 0.f;
#pragma unroll
        for (int nt = 0; nt < 8; nt++) {
            sc[nt][0] = __expf(sc[nt][0] - mn0);
            sc[nt][1] = __expf(sc[nt][1] - mn0);
            sc[nt][2] = __expf(sc[nt][2] - mn1);
            sc[nt][3] = __expf(sc[nt][3] - mn1);
            lt0 += sc[nt][0] + sc[nt][1];
            lt1 += sc[nt][2] + sc[nt][3];
        }
        lt0 += __shfl_xor_sync(0xffffffffu, lt0, 1);
        lt0 += __shfl_xor_sync(0xffffffffu, lt0, 2);
        lt1 += __shfl_xor_sync(0xffffffffu, lt1, 1);
        lt1 += __shfl_xor_sync(0xffffffffu, lt1, 2);
        l0 = l0 * sc0 + lt0; m0 = mn0;
        l1 = l1 * sc1 + lt1; m1 = mn1;
#pragma unroll
        for (int nt = 0; nt < 8; nt++) {
            oacc[nt][0] *= sc0; oacc[nt][1] *= sc0;
            oacc[nt][2] *= sc1; oacc[nt][3] *= sc1;
        }

        __syncthreads();   // everyone done reading K from KP
        {
            float* pr0 = KP + (w * 16 + qrow) * KP_STRIDE;
            float* pr1 = KP + (w * 16 + qrow + 8) * KP_STRIDE;
#pragma unroll
            for (int nt = 0; nt < 8; nt++) {
                const int cc = nt * 8 + 2 * qcol;
                *(float2*)(pr0 + cc) = make_float2(sc[nt][0], sc[nt][1]);
                *(float2*)(pr1 + cc) = make_float2(sc[nt][2], sc[nt][3]);
            }
        }
        __syncwarp();
        uint32_t pf[8][4];
        {
            const int r0 = w * 16 + qrow;
#pragma unroll
            for (int ks = 0; ks < 8; ks++) {
                pf[ks][0] = __float_as_uint(KP[r0 * KP_STRIDE + ks * 8 + qcol]);
                pf[ks][1] = __float_as_uint(KP[(r0 + 8) * KP_STRIDE + ks * 8 + qcol]);
                pf[ks][2] = __float_as_uint(KP[r0 * KP_STRIDE + ks * 8 + qcol + 4]);
                pf[ks][3] = __float_as_uint(KP[(r0 + 8) * KP_STRIDE + ks * 8 + qcol + 4]);
            }
        }
#pragma unroll
        for (int nt = 0; nt < 8; nt++) {
#pragma unroll
            for (int ks = 0; ks < 8; ks++) {
                const float* vr = Vs + (ks * 8 + qcol) * V_STRIDE + nt * 8 + qrow;
                const uint32_t b0 = __float_as_uint(vr[0]);
                const uint32_t b1 = __float_as_uint(*(vr + 4 * V_STRIDE));
                mma_tf32_16x8x8(oacc[nt][0], oacc[nt][1], oacc[nt][2], oacc[nt][3],
                                pf[ks][0], pf[ks][1], pf[ks][2], pf[ks][3], b0, b1);
            }
        }
    }

    const float inv0 = (mq0 != 0) ? (1.0f / l0) : 0.f;
    const float inv1 = (mq1 != 0) ? (1.0f / l1) : 0.f;
    float* o0 = O + base + (size_t)qg0 * Dc;
    float* o1 = O + base + (size_t)qg1 * Dc;
#pragma unroll
    for (int nt = 0; nt < 8; nt++) {
        const int cc = nt * 8 + 2 * qcol;
        *(float2*)(o0 + cc) = make_float2(oacc[nt][0] * inv0, oacc[nt][1] * inv0);
        *(float2*)(o1 + cc) = make_float2(oacc[nt][2] * inv1, oacc[nt][3] * inv1);
    }
}

// ---------------- layernorm ----------------
__device__ __forceinline__ float block_sum(float v, float* red) {
#pragma unroll
    for (int o = 16; o > 0; o >>= 1) v += __shfl_xor_sync(0xffffffffu, v, o);
    const int lane = threadIdx.x & 31, w = threadIdx.x >> 5;
    __syncthreads();
    if (lane == 0) red[w] = v;
    __syncthreads();
    float s = 0.f;
#pragma unroll
    for (int i = 0; i < 8; i++) s += red[i];
    return s;
}

__global__ void __launch_bounds__(256) ln12_kernel(
    const float* __restrict__ x, const float* __restrict__ o,
    const float* __restrict__ cond,
    const float* __restrict__ g1, const float* __restrict__ b1,
    const float* __restrict__ g2, const float* __restrict__ b2,
    float* __restrict__ out2)
{
    __shared__ float red[8];
    const int row = blockIdx.x;
    const int bb  = row >> 10;
    const int tid = threadIdx.x;
    const float* xr = x + (size_t)row * Dc;
    const float* orr = o + (size_t)row * Dc;
    float t[4];
    float s = 0.f;
#pragma unroll
    for (int k = 0; k < 4; k++) {
        const int d = tid + k * 256;
        t[k] = xr[d] + orr[d];
        s += t[k];
    }
    float mu = block_sum(s, red) * (1.f / 1024.f);
    float vs = 0.f;
#pragma unroll
    for (int k = 0; k < 4; k++) { float dv = t[k] - mu; vs += dv * dv; }
    float var = block_sum(vs, red) * (1.f / 1024.f);
    float inv = rsqrtf(var + 1e-3f);
#pragma unroll
    for (int k = 0; k < 4; k++) {
        const int d = tid + k * 256;
        float y = (t[k] - mu) * inv * g1[d] + b1[d];
        t[k] = y + cond[bb * Dc + d];
    }
    s = 0.f;
#pragma unroll
    for (int k = 0; k < 4; k++) s += t[k];
    mu = block_sum(s, red) * (1.f / 1024.f);
    vs = 0.f;
#pragma unroll
    for (int k = 0; k < 4; k++) { float dv = t[k] - mu; vs += dv * dv; }
    var = block_sum(vs, red) * (1.f / 1024.f);
    inv = rsqrtf(var + 1e-3f);
#pragma unroll
    for (int k = 0; k < 4; k++) {
        const int d = tid + k * 256;
        out2[(size_t)row * Dc + d] = (t[k] - mu) * inv * g2[d] + b2[d];
    }
}

__global__ void __launch_bounds__(256) ln3_kernel(
    const float* __restrict__ a, const float* __restrict__ f,
    const float* __restrict__ g3, const float* __restrict__ b3,
    float* __restrict__ out)
{
    __shared__ float red[8];
    const int row = blockIdx.x;
    const int tid = threadIdx.x;
    const float* ar = a + (size_t)row * Dc;
    const float* fr = f + (size_t)row * Dc;
    float t[4];
    float s = 0.f;
#pragma unroll
    for (int k = 0; k < 4; k++) {
        const int d = tid + k * 256;
        t[k] = ar[d] + fr[d];
        s += t[k];
    }
    float mu = block_sum(s, red) * (1.f / 1024.f);
    float vs = 0.f;
#pragma unroll
    for (int k = 0; k < 4; k++) { float dv = t[k] - mu; vs += dv * dv; }
    float var = block_sum(vs, red) * (1.f / 1024.f);
    float inv = rsqrtf(var + 1e-3f);
#pragma unroll
    for (int k = 0; k < 4; k++) {
        const int d = tid + k * 256;
        out[(size_t)row * Dc + d] = (t[k] - mu) * inv * g3[d] + b3[d];
    }
}

// ---------------- launch ----------------
extern "C" void kernel_launch(void* const* d_in, const int* in_sizes, int n_in,
                              void* d_out, int out_size) {
    const float* x    = (const float*)d_in[0];
    const float* z    = (const float*)d_in[1];
    const float* cond = (const float*)d_in[2];
    const int*   xm   = (const int*)  d_in[3];
    const float* WQ   = (const float*)d_in[4];
    const float* WK   = (const float*)d_in[5];
    const float* WV   = (const float*)d_in[6];
    const float* W1   = (const float*)d_in[7];
    const float* b1   = (const float*)d_in[8];
    const float* W2   = (const float*)d_in[9];
    const float* b2   = (const float*)d_in[10];
    const float* g1   = (const float*)d_in[11];
    const float* be1  = (const float*)d_in[12];
    const float* g2   = (const float*)d_in[13];
    const float* be2  = (const float*)d_in[14];
    const float* g3   = (const float*)d_in[15];
    const float* be3  = (const float*)d_in[16];
    float* out = (float*)d_out;

    float *pQ, *pK, *pV, *pO, *pO2, *pH, *pF;
    cudaGetSymbolAddress((void**)&pQ,  g_Q);
    cudaGetSymbolAddress((void**)&pK,  g_K);
    cudaGetSymbolAddress((void**)&pV,  g_V);
    cudaGetSymbolAddress((void**)&pO,  g_O);
    cudaGetSymbolAddress((void**)&pO2, g_O2);
    cudaGetSymbolAddress((void**)&pH,  g_H);
    cudaGetSymbolAddress((void**)&pF,  g_F);

    cudaFuncSetAttribute(mma_gemm<0>, cudaFuncAttributeMaxDynamicSharedMemorySize,
                         GEMM_SMEM_BYTES);
    cudaFuncSetAttribute(mma_gemm<1>, cudaFuncAttributeMaxDynamicSharedMemorySize,
                         GEMM_SMEM_BYTES);

    mma_gemm<0><<<dim3(Dc / 128, Mrows / 128), 128, GEMM_SMEM_BYTES>>>(
        x, nullptr, WQ, nullptr, pQ, Dc, Dc, 0);
    mma_gemm<0><<<dim3(Dc / 128, Mrows / 128), 128, GEMM_SMEM_BYTES>>>(
        x, nullptr, WK, nullptr, pK, Dc, Dc, 0);
    mma_gemm<0><<<dim3(Dc / 128, Mrows / 128), 128, GEMM_SMEM_BYTES>>>(
        x, nullptr, WV, nullptr, pV, Dc, Dc, 0);

    attn_kernel<<<dim3(Sc / 64, Hc, Bc), 128>>>(pQ, pK, pV, xm, pO);

    ln12_kernel<<<Mrows, 256>>>(x, pO, cond, g1, be1, g2, be2, pO2);

    mma_gemm<1><<<dim3(DFFc / 128, Mrows / 128), 128, GEMM_SMEM_BYTES>>>(
        pO2, z, W1, b1, pH, DFFc, Dc + DLATc, 1);
    mma_gemm<0><<<dim3(Dc / 128, Mrows / 128), 128, GEMM_SMEM_BYTES>>>(
        pH, nullptr, W2, b2, pF, Dc, DFFc, 0);

    ln3_kernel<<<Mrows, 256>>>(pO2, pF, g3, be3, out);
}